// round 5
// baseline (speedup 1.0000x reference)
#include <cuda_runtime.h>
#include <stdint.h>

// RecyclingEmbedder: out[i,j,:] = W[:,bin(d_ij)] + b  (b only if no bin hit)
//
// R4 ncu: DRAM 75.1% binding, issue only 14% — store-drain bound. R5 change:
// contiguous ownership. Each warp handles 8 CONSECUTIVE 32-pair groups
// (one 128 KB contiguous output span) instead of grid-striding 148 MB apart,
// improving DRAM row-buffer locality for the pure-write stream.

#define N_PTS   1536
#define D_PAIR  128
#define GROUPS_PER_ROW (N_PTS / 32)          // 48
#define NGROUPS (N_PTS * GROUPS_PER_ROW)     // 73728
#define GROUPS_PER_WARP 8                    // 8 * 16KB = 128KB contiguous/warp
#define NWARPS_PER_BLOCK 8
#define BLOCK_THREADS (NWARPS_PER_BLOCK * 32)

__global__ __launch_bounds__(BLOCK_THREADS)
void recycling_embedder_kernel(const float* __restrict__ x,
                               const float* __restrict__ W,
                               const float* __restrict__ b,
                               float* __restrict__ out)
{
    __shared__ float s_table[16 * D_PAIR];   // 8 KB:  row k = W[:,k]+b, row 15 = b
    __shared__ float s_x[N_PTS * 3];         // 18 KB

    const int tid = threadIdx.x;

    // table[k][p] = W[p*15+k] + b[p] for k<15; table[15][p] = b[p].
    for (int idx = tid; idx < 16 * D_PAIR; idx += BLOCK_THREADS) {
        int k = idx >> 7;
        int p = idx & (D_PAIR - 1);
        float v = b[p];
        if (k < 15) v += W[p * 15 + k];
        s_table[idx] = v;
    }
    for (int idx = tid; idx < N_PTS * 3; idx += BLOCK_THREADS) {
        s_x[idx] = x[idx];
    }
    __syncthreads();

    const int lane = tid & 31;
    const int warp = tid >> 5;
    const int gwarp = blockIdx.x * NWARPS_PER_BLOCK + warp;

    // Hot rows in registers: row 15 (b only, ~83%) and row 0 (~15%).
    const float4 v15 = *reinterpret_cast<const float4*>(&s_table[15 * D_PAIR + lane * 4]);
    const float4 v0  = *reinterpret_cast<const float4*>(&s_table[ 0 * D_PAIR + lane * 4]);

    // Contiguous chunk of 8 groups per warp (warps beyond 9216 get no work).
    const int gbase = gwarp * GROUPS_PER_WARP;

    #pragma unroll 1
    for (int t = 0; t < GROUPS_PER_WARP; t++) {
        const int g = gbase + t;
        if (g >= NGROUPS) break;
        const int i  = g / GROUPS_PER_ROW;
        const int j0 = (g - i * GROUPS_PER_ROW) * 32;
        const int j  = j0 + lane;

        // Phase 1: one pair per lane. Match reference rounding exactly:
        // no FMA contraction, sum order (dx^2 + dy^2) + dz^2.
        float dx = s_x[i * 3 + 0] - s_x[j * 3 + 0];
        float dy = s_x[i * 3 + 1] - s_x[j * 3 + 1];
        float dz = s_x[i * 3 + 2] - s_x[j * 3 + 2];
        float d  = __fadd_rn(__fadd_rn(__fmul_rn(dx, dx), __fmul_rn(dy, dy)),
                             __fmul_rn(dz, dz));

        int bi = 15;  // default: no bin hit -> b-only row
        #pragma unroll
        for (int k = 0; k < 15; k++) {
            const float e0 = 3.25f + 1.25f * (float)k;
            const float lo = e0 * e0;                       // folded at compile time
            const float e1 = 3.25f + 1.25f * (float)(k + 1);
            const float hi = (k == 14) ? 100000000.0f : e1 * e1;
            if (d > lo && d < hi) bi = k;
        }

        // Classify all 32 rows with two ballots (warp-uniform masks).
        const unsigned m15 = __ballot_sync(0xffffffffu, bi == 15);
        const unsigned m0  = __ballot_sync(0xffffffffu, bi == 0);

        // Phase 2: stream 32 rows (16 KB contiguous). Rare rows (~2%) take a
        // warp-uniform shfl + LDS.
        float4* dst = reinterpret_cast<float4*>(
                          out + ((size_t)i * N_PTS + j0) * D_PAIR) + lane;
        #pragma unroll
        for (int p = 0; p < 32; p++) {
            float4 v;
            if ((m15 >> p) & 1u) {
                v = v15;
            } else if ((m0 >> p) & 1u) {
                v = v0;
            } else {
                int bp = __shfl_sync(0xffffffffu, bi, p);   // uniform branch: safe
                v = *reinterpret_cast<const float4*>(
                        &s_table[bp * D_PAIR + lane * 4]);
            }
            __stcs(&dst[p * (D_PAIR / 4)], v);   // STG.E.128 streaming
        }
    }
}

extern "C" void kernel_launch(void* const* d_in, const int* in_sizes, int n_in,
                              void* d_out, int out_size)
{
    const float* x = (const float*)d_in[0];   // [1536, 3]
    const float* W = (const float*)d_in[1];   // [128, 15]
    const float* b = (const float*)d_in[2];   // [128]
    float* out = (float*)d_out;               // [1536, 1536, 128]

    // 9216 working warps * 8 groups = 73728 groups exactly; 1184 blocks keeps
    // all 148 SMs populated (trailing 256 warps simply exit).
    recycling_embedder_kernel<<<1184, BLOCK_THREADS>>>(x, W, b, out);
}

// round 6
// speedup vs baseline: 1.0802x; 1.0802x over previous
#include <cuda_runtime.h>
#include <stdint.h>

// RecyclingEmbedder: out[i,j,:] = W[:,bin(d_ij)] + b  (b only if no bin hit)
//
// R5 post-mortem: contiguous per-warp chunks REGRESSED (occ 85->73, DRAM
// 75->72.8). R4 grid-stride mapping is chip-wide optimal: each round of
// concurrent warps covers one contiguous ~148MB span. R6 = R4 revert +
// software-pipelined phase 1 (compute next group's bins/ballots during the
// current group's 32-store burst) to hide the ~100-cycle LDS+compare+ballot
// chain behind store drain.

#define N_PTS   1536
#define D_PAIR  128
#define GROUPS_PER_ROW (N_PTS / 32)          // 48
#define NGROUPS (N_PTS * GROUPS_PER_ROW)     // 73728
#define NWARPS_PER_BLOCK 8
#define BLOCK_THREADS (NWARPS_PER_BLOCK * 32)

struct GroupPlan {
    unsigned m15;   // lanes whose row is b-only
    unsigned m0;    // lanes whose row is bin 0
    int      bi;    // this lane's bin (for rare-path shfl)
    int      i, j0; // group coordinates
};

__device__ __forceinline__ GroupPlan plan_group(int g, int lane,
                                                const float* __restrict__ s_x)
{
    GroupPlan pl;
    pl.i  = g / GROUPS_PER_ROW;
    pl.j0 = (g - pl.i * GROUPS_PER_ROW) * 32;
    const int j = pl.j0 + lane;

    // Match reference rounding exactly: no FMA contraction,
    // sum order (dx^2 + dy^2) + dz^2.
    float dx = s_x[pl.i * 3 + 0] - s_x[j * 3 + 0];
    float dy = s_x[pl.i * 3 + 1] - s_x[j * 3 + 1];
    float dz = s_x[pl.i * 3 + 2] - s_x[j * 3 + 2];
    float d  = __fadd_rn(__fadd_rn(__fmul_rn(dx, dx), __fmul_rn(dy, dy)),
                         __fmul_rn(dz, dz));

    int bi = 15;  // default: no bin hit -> b-only row
    #pragma unroll
    for (int k = 0; k < 15; k++) {
        const float e0 = 3.25f + 1.25f * (float)k;
        const float lo = e0 * e0;                        // folded at compile time
        const float e1 = 3.25f + 1.25f * (float)(k + 1);
        const float hi = (k == 14) ? 100000000.0f : e1 * e1;
        if (d > lo && d < hi) bi = k;
    }
    pl.bi  = bi;
    pl.m15 = __ballot_sync(0xffffffffu, bi == 15);
    pl.m0  = __ballot_sync(0xffffffffu, bi == 0);
    return pl;
}

__global__ __launch_bounds__(BLOCK_THREADS)
void recycling_embedder_kernel(const float* __restrict__ x,
                               const float* __restrict__ W,
                               const float* __restrict__ b,
                               float* __restrict__ out)
{
    __shared__ float s_table[16 * D_PAIR];   // 8 KB:  row k = W[:,k]+b, row 15 = b
    __shared__ float s_x[N_PTS * 3];         // 18 KB

    const int tid = threadIdx.x;

    // table[k][p] = W[p*15+k] + b[p] for k<15; table[15][p] = b[p].
    for (int idx = tid; idx < 16 * D_PAIR; idx += BLOCK_THREADS) {
        int k = idx >> 7;
        int p = idx & (D_PAIR - 1);
        float v = b[p];
        if (k < 15) v += W[p * 15 + k];
        s_table[idx] = v;
    }
    for (int idx = tid; idx < N_PTS * 3; idx += BLOCK_THREADS) {
        s_x[idx] = x[idx];
    }
    __syncthreads();

    const int lane = tid & 31;
    const int warp = tid >> 5;
    const int gwarp  = blockIdx.x * NWARPS_PER_BLOCK + warp;
    const int nwarps = gridDim.x * NWARPS_PER_BLOCK;

    // Hot rows in registers: row 15 (b only, ~83%) and row 0 (~15%).
    const float4 v15 = *reinterpret_cast<const float4*>(&s_table[15 * D_PAIR + lane * 4]);
    const float4 v0  = *reinterpret_cast<const float4*>(&s_table[ 0 * D_PAIR + lane * 4]);

    if (gwarp >= NGROUPS) return;

    // Software pipeline: plan for group g is ready before its store burst.
    GroupPlan cur = plan_group(gwarp, lane, s_x);

    for (int g = gwarp; g < NGROUPS; g += nwarps) {
        const int gnext = g + nwarps;

        float4* dst = reinterpret_cast<float4*>(
                          out + ((size_t)cur.i * N_PTS + cur.j0) * D_PAIR) + lane;
        const unsigned m15 = cur.m15;
        const unsigned m0  = cur.m0;
        const int      bic = cur.bi;

        // Overlap: compute next group's plan before draining this burst.
        GroupPlan nxt;
        if (gnext < NGROUPS) nxt = plan_group(gnext, lane, s_x);

        // Stream 32 rows (16 KB contiguous). Rare rows (~2%) take a
        // warp-uniform shfl + LDS; the branch is divergence-free.
        #pragma unroll
        for (int p = 0; p < 32; p++) {
            float4 v;
            if ((m15 >> p) & 1u) {
                v = v15;
            } else if ((m0 >> p) & 1u) {
                v = v0;
            } else {
                int bp = __shfl_sync(0xffffffffu, bic, p);
                v = *reinterpret_cast<const float4*>(
                        &s_table[bp * D_PAIR + lane * 4]);
            }
            __stcs(&dst[p * (D_PAIR / 4)], v);   // STG.E.128 streaming
        }

        cur = nxt;
    }
}

extern "C" void kernel_launch(void* const* d_in, const int* in_sizes, int n_in,
                              void* d_out, int out_size)
{
    const float* x = (const float*)d_in[0];   // [1536, 3]
    const float* W = (const float*)d_in[1];   // [128, 15]
    const float* b = (const float*)d_in[2];   // [128]
    float* out = (float*)d_out;               // [1536, 1536, 128]

    // 1184 = 148 SMs * 8 blocks (27KB smem each): exactly one resident wave;
    // grid-stride rounds sweep contiguous ~148MB output spans chip-wide.
    recycling_embedder_kernel<<<1184, BLOCK_THREADS>>>(x, W, b, out);
}